// round 15
// baseline (speedup 1.0000x reference)
#include <cuda_runtime.h>
#include <cuda_fp16.h>
#include <cstdint>
#include <cstddef>

// ---------------------------------------------------------------------------
// GCN 2-layer forward on GB300 — fp16 HMMA GEMMs + gather SpMM.
//   h1 = x @ W1           (fp16 HMMA, BM=128)              [k_hgemm1]
//   a1 = relu(Ahat h1+b1) (fp16-stored)                    [k_spmm1]
//   h2 = a1 @ W2          (fp16 HMMA, fp16 A path)         [k_hgemm2]
//   out = Ahat h2 + b2    (fp32 out)                       [k_spmm2]
// R15: SpMM inner loops unrolled x4 with batched record loads + gathers
// (MLP 1-2 -> 4+) and dual accumulators. CSR build still overlapped with
// GEMM1 on a side stream (R14).
// ---------------------------------------------------------------------------

#define NNODES 100000
#define NEDGES 1600000
#define NNZ    (NNODES + NEDGES)

__device__ int   g_deg[NNODES];
__device__ int   g_fill[NNODES];
__device__ int   g_rowstart[NNODES + 1];
__device__ int   g_bsums[256];
__device__ float g_dinv[NNODES];
__device__ int2  g_cw[NNZ];                     // .x = col, .y = wgt bits
__device__ __half g_h1[(size_t)NNODES * 128];   // h1 (fp16)
__device__ __half g_a1[(size_t)NNODES * 128];   // a1 (fp16)
__device__ __half g_h2[(size_t)NNODES * 64];    // h2 (fp16)
// W transposed K-major [N][K], fp16
__device__ __half g_w1[128 * 256];
__device__ __half g_w2[64 * 128];

// ------------------------------ helpers ------------------------------------

__device__ __forceinline__ uint32_t smem_u32(const void* p) {
    uint32_t a;
    asm("{ .reg .u64 t; cvta.to.shared.u64 t, %1; cvt.u32.u64 %0, t; }"
        : "=r"(a) : "l"(p));
    return a;
}

#define LDMATRIX_X4(r, addr) \
    asm volatile("ldmatrix.sync.aligned.m8n8.x4.shared.b16 {%0,%1,%2,%3}, [%4];" \
                 : "=r"((r)[0]), "=r"((r)[1]), "=r"((r)[2]), "=r"((r)[3]) \
                 : "r"(addr))

#define MMA_F16(c, a, b0, b1) \
    asm volatile( \
        "mma.sync.aligned.m16n8k16.row.col.f32.f16.f16.f32 " \
        "{%0,%1,%2,%3}, {%4,%5,%6,%7}, {%8,%9}, {%0,%1,%2,%3};" \
        : "+f"((c)[0]), "+f"((c)[1]), "+f"((c)[2]), "+f"((c)[3]) \
        : "r"((a)[0]), "r"((a)[1]), "r"((a)[2]), "r"((a)[3]), \
          "r"(b0), "r"(b1))

// ldmatrix x4 address, 64B-row buffer: swizzle kg ^= (row>>1)&3
__device__ __forceinline__ uint32_t lm_addr64(uint32_t buf, int rowbase, int ks,
                                              int lane) {
    int row = rowbase + (lane & 15);
    int kg = ks * 2 + (lane >> 4);
    return buf + row * 64 + (((kg ^ ((row >> 1) & 3))) << 4);
}

// ---------------------------------------------------------------------------
// CSR construction
// ---------------------------------------------------------------------------

// W convert (both layers) + deg init, one launch
__global__ void k_wcvt_init(const float* __restrict__ W1,
                            const float* __restrict__ W2, int n) {
    int idx = blockIdx.x * blockDim.x + threadIdx.x;
    if (idx < 128 * 256) {                 // W1: K=256, N=128
        int nn = idx / 256, k = idx % 256;
        g_w1[idx] = __float2half_rn(W1[k * 128 + nn]);
    } else if (idx < 128 * 256 + 64 * 128) {  // W2: K=128, N=64
        int j = idx - 128 * 256;
        int nn = j / 128, k = j % 128;
        g_w2[j] = __float2half_rn(W2[k * 64 + nn]);
    }
    if (idx < n) g_deg[idx] = 1;           // self loop
}

__global__ void k_count(const int* __restrict__ dst, int e) {
    int i = blockIdx.x * blockDim.x + threadIdx.x;
    if (i < e) atomicAdd(&g_deg[dst[i]], 1);
}

__global__ void k_scan1(int n) {
    __shared__ int s[1024];
    int gid = blockIdx.x * 1024 + threadIdx.x;
    int v = (gid < n) ? g_deg[gid] : 0;
    s[threadIdx.x] = v;
    __syncthreads();
    for (int off = 1; off < 1024; off <<= 1) {
        int t = (threadIdx.x >= off) ? s[threadIdx.x - off] : 0;
        __syncthreads();
        s[threadIdx.x] += t;
        __syncthreads();
    }
    if (gid < n) g_rowstart[gid] = s[threadIdx.x] - v;
    if (threadIdx.x == 1023) g_bsums[blockIdx.x] = s[1023];
}

__global__ void k_scanfill(int n, int nb) {
    __shared__ int soff;
    int gid = blockIdx.x * 1024 + threadIdx.x;
    if (threadIdx.x == 0) {
        int o = 0;
        for (int b = 0; b < (int)blockIdx.x; b++) o += g_bsums[b];
        soff = o;
    }
    __syncthreads();
    if (gid < n) {
        int rs = g_rowstart[gid] + soff;
        g_rowstart[gid] = rs;
        float d = rsqrtf((float)g_deg[gid]);
        g_dinv[gid] = d;
        g_cw[rs] = make_int2(gid, __float_as_int(d * d));
        g_fill[gid] = 1;
    }
    if (gid == 0) {
        int o = 0;
        for (int b = 0; b < nb; b++) o += g_bsums[b];
        g_rowstart[n] = o;
    }
}

__global__ void k_fill_edges(const int* __restrict__ src,
                             const int* __restrict__ dst, int e) {
    int i = blockIdx.x * blockDim.x + threadIdx.x;
    if (i < e) {
        int s = src[i];
        int d = dst[i];
        int p = g_rowstart[d] + atomicAdd(&g_fill[d], 1);
        g_cw[p] = make_int2(s, __float_as_int(g_dinv[s] * g_dinv[d]));
    }
}

// ---------------------------------------------------------------------------
// GEMM1: h1[M,128] = x[M,256](fp32) @ W1, fp16 HMMA, BM=128, reg dbuf.
// ---------------------------------------------------------------------------

__global__ void __launch_bounds__(256, 2) k_hgemm1(const float* __restrict__ A,
                                                   int M) {
    constexpr int N_ = 128, K_ = 256;
    constexpr int NCHUNK = K_ / 32;
    constexpr int NT16 = N_ / 32;
    constexpr int NBQ = 2;
    constexpr int OFF_B = 8192;

    __shared__ __align__(128) char smem[8192 + N_ * 64];

    const __half* __restrict__ Bw = g_w1;
    const uint32_t sb = smem_u32(smem);
    const int tid = threadIdx.x;
    const int wid = tid >> 5, lane = tid & 31;
    const int wm = wid & 3, wn = wid >> 2;
    const int m0 = blockIdx.x * 128;

    float acc[2][N_ / 16][4];
#pragma unroll
    for (int i = 0; i < 2; i++)
#pragma unroll
        for (int j = 0; j < N_ / 16; j++)
#pragma unroll
            for (int q = 0; q < 4; q++) acc[i][j][q] = 0.f;

    const int a_row[4] = {tid >> 3, (tid + 256) >> 3, (tid + 512) >> 3,
                          (tid + 768) >> 3};
    const int a_f4 = tid & 7;

    float4 pa[4];
    uint4 pb[NBQ];
#pragma unroll
    for (int i = 0; i < 4; i++) {
        int gr = m0 + a_row[i];
        pa[i] = make_float4(0.f, 0.f, 0.f, 0.f);
        if (gr < M) pa[i] = *(const float4*)(A + (size_t)gr * K_ + a_f4 * 4);
    }
#pragma unroll
    for (int i = 0; i < NBQ; i++) {
        int idx = tid + i * 256;
        int row = idx >> 2, kg = idx & 3;
        pb[i] = *(const uint4*)(Bw + (size_t)row * K_ + kg * 8);
    }

    for (int chunk = 0; chunk < NCHUNK; chunk++) {
#pragma unroll
        for (int i = 0; i < 4; i++) {
            float4 v = pa[i];
            int row = a_row[i];
            __half2 p0 = __floats2half2_rn(v.x, v.y);
            __half2 p1 = __floats2half2_rn(v.z, v.w);
            int kg = a_f4 >> 1, half = a_f4 & 1;
            uint32_t byte = row * 64 + ((kg ^ ((row >> 1) & 3)) << 4) + half * 8;
            *(uint2*)(smem + byte) = make_uint2(*(uint32_t*)&p0, *(uint32_t*)&p1);
        }
#pragma unroll
        for (int i = 0; i < NBQ; i++) {
            int idx = tid + i * 256;
            int row = idx >> 2, kg = idx & 3;
            uint32_t byte = row * 64 + ((kg ^ ((row >> 1) & 3)) << 4);
            *(uint4*)(smem + OFF_B + byte) = pb[i];
        }
        __syncthreads();

        if (chunk + 1 < NCHUNK) {
            const int k0 = (chunk + 1) * 32;
#pragma unroll
            for (int i = 0; i < 4; i++) {
                int gr = m0 + a_row[i];
                pa[i] = make_float4(0.f, 0.f, 0.f, 0.f);
                if (gr < M)
                    pa[i] = *(const float4*)(A + (size_t)gr * K_ + k0 + a_f4 * 4);
            }
#pragma unroll
            for (int i = 0; i < NBQ; i++) {
                int idx = tid + i * 256;
                int row = idx >> 2, kg = idx & 3;
                pb[i] = *(const uint4*)(Bw + (size_t)row * K_ + k0 + kg * 8);
            }
        }

#pragma unroll
        for (int ks = 0; ks < 2; ks++) {
            uint32_t am[2][4];
#pragma unroll
            for (int mt = 0; mt < 2; mt++) {
                LDMATRIX_X4(am[mt], lm_addr64(sb, wm * 32 + mt * 16, ks, lane));
            }
#pragma unroll
            for (int nt = 0; nt < NT16; nt++) {
                uint32_t bm[4];
                LDMATRIX_X4(bm, lm_addr64(sb + OFF_B, wn * (N_ / 2) + nt * 16,
                                          ks, lane));
#pragma unroll
                for (int mt = 0; mt < 2; mt++) {
                    MMA_F16(acc[mt][nt * 2 + 0], am[mt], bm[0], bm[2]);
                    MMA_F16(acc[mt][nt * 2 + 1], am[mt], bm[1], bm[3]);
                }
            }
        }
        __syncthreads();
    }

#pragma unroll
    for (int mt = 0; mt < 2; mt++) {
#pragma unroll
        for (int nt8 = 0; nt8 < N_ / 16; nt8++) {
            const float* c = acc[mt][nt8];
            int row0 = m0 + wm * 32 + mt * 16 + (lane >> 2);
            int col = wn * (N_ / 2) + nt8 * 8 + 2 * (lane & 3);
            __half2 p0 = __floats2half2_rn(c[0], c[1]);
            __half2 p1 = __floats2half2_rn(c[2], c[3]);
            if (row0 < M)
                *(uint32_t*)(g_h1 + (size_t)row0 * N_ + col) = *(uint32_t*)&p0;
            if (row0 + 8 < M)
                *(uint32_t*)(g_h1 + (size_t)(row0 + 8) * N_ + col) = *(uint32_t*)&p1;
        }
    }
}

// ---------------------------------------------------------------------------
// GEMM2: h2[M,64] = a1[M,128](fp16) @ W2, fp16 A path.
// ---------------------------------------------------------------------------

__global__ void __launch_bounds__(256, 2) k_hgemm2(int M) {
    constexpr int N_ = 64, K_ = 128;
    constexpr int NCHUNK = K_ / 32;      // 4
    constexpr int NT16 = N_ / 32;        // 2
    constexpr int OFF_B = 8192;

    __shared__ __align__(128) char smem[8192 + N_ * 64];

    const __half* __restrict__ A = g_a1;
    const __half* __restrict__ Bw = g_w2;
    const uint32_t sb = smem_u32(smem);
    const int tid = threadIdx.x;
    const int wid = tid >> 5, lane = tid & 31;
    const int wm = wid & 3, wn = wid >> 2;
    const int m0 = blockIdx.x * 128;

    float acc[2][N_ / 16][4];
#pragma unroll
    for (int i = 0; i < 2; i++)
#pragma unroll
        for (int j = 0; j < N_ / 16; j++)
#pragma unroll
            for (int q = 0; q < 4; q++) acc[i][j][q] = 0.f;

    const int a_row[2] = {tid >> 2, (tid + 256) >> 2};
    const int a_kg = tid & 3;

    uint4 pa[2];
    uint4 pb;
#pragma unroll
    for (int i = 0; i < 2; i++) {
        int gr = m0 + a_row[i];
        pa[i] = make_uint4(0u, 0u, 0u, 0u);
        if (gr < M) pa[i] = *(const uint4*)(A + (size_t)gr * K_ + a_kg * 8);
    }
    {
        int row = tid >> 2, kg = tid & 3;
        pb = *(const uint4*)(Bw + (size_t)row * K_ + kg * 8);
    }

    for (int chunk = 0; chunk < NCHUNK; chunk++) {
#pragma unroll
        for (int i = 0; i < 2; i++) {
            int row = a_row[i];
            uint32_t byte = row * 64 + ((a_kg ^ ((row >> 1) & 3)) << 4);
            *(uint4*)(smem + byte) = pa[i];
        }
        {
            int row = tid >> 2, kg = tid & 3;
            uint32_t byte = row * 64 + ((kg ^ ((row >> 1) & 3)) << 4);
            *(uint4*)(smem + OFF_B + byte) = pb;
        }
        __syncthreads();

        if (chunk + 1 < NCHUNK) {
            const int k0 = (chunk + 1) * 32;
#pragma unroll
            for (int i = 0; i < 2; i++) {
                int gr = m0 + a_row[i];
                pa[i] = make_uint4(0u, 0u, 0u, 0u);
                if (gr < M)
                    pa[i] = *(const uint4*)(A + (size_t)gr * K_ + k0 + a_kg * 8);
            }
            int row = tid >> 2, kg = tid & 3;
            pb = *(const uint4*)(Bw + (size_t)row * K_ + k0 + kg * 8);
        }

#pragma unroll
        for (int ks = 0; ks < 2; ks++) {
            uint32_t am[2][4];
#pragma unroll
            for (int mt = 0; mt < 2; mt++) {
                LDMATRIX_X4(am[mt], lm_addr64(sb, wm * 32 + mt * 16, ks, lane));
            }
#pragma unroll
            for (int nt = 0; nt < NT16; nt++) {
                uint32_t bm[4];
                LDMATRIX_X4(bm, lm_addr64(sb + OFF_B, wn * (N_ / 2) + nt * 16,
                                          ks, lane));
#pragma unroll
                for (int mt = 0; mt < 2; mt++) {
                    MMA_F16(acc[mt][nt * 2 + 0], am[mt], bm[0], bm[2]);
                    MMA_F16(acc[mt][nt * 2 + 1], am[mt], bm[1], bm[3]);
                }
            }
        }
        __syncthreads();
    }

#pragma unroll
    for (int mt = 0; mt < 2; mt++) {
#pragma unroll
        for (int nt8 = 0; nt8 < N_ / 16; nt8++) {
            const float* c = acc[mt][nt8];
            int row0 = m0 + wm * 32 + mt * 16 + (lane >> 2);
            int col = wn * (N_ / 2) + nt8 * 8 + 2 * (lane & 3);
            __half2 p0 = __floats2half2_rn(c[0], c[1]);
            __half2 p1 = __floats2half2_rn(c[2], c[3]);
            if (row0 < M)
                *(uint32_t*)(g_h2 + (size_t)row0 * N_ + col) = *(uint32_t*)&p0;
            if (row0 + 8 < M)
                *(uint32_t*)(g_h2 + (size_t)(row0 + 8) * N_ + col) = *(uint32_t*)&p1;
        }
    }
}

// ---------------------------------------------------------------------------
// SpMM layer 1: a1 = relu(Ahat @ h1(fp16) + b1), fp16-stored. warp/node.
// Unroll x4: batch 4 edge records + 4 gathers in flight, dual accumulators.
// ---------------------------------------------------------------------------

__launch_bounds__(256)
__global__ void k_spmm1(const float* __restrict__ bias, int n) {
    int w = (blockIdx.x * 256 + threadIdx.x) >> 5;
    int lane = threadIdx.x & 31;
    if (w >= n) return;
    int beg = g_rowstart[w], end = g_rowstart[w + 1];

    float4 accA = make_float4(0.f, 0.f, 0.f, 0.f);
    float4 accB = make_float4(0.f, 0.f, 0.f, 0.f);
    const __half* hb = g_h1 + lane * 4;

    int e = beg;
    for (; e + 4 <= end; e += 4) {
        int2 cw0 = g_cw[e + 0];
        int2 cw1 = g_cw[e + 1];
        int2 cw2 = g_cw[e + 2];
        int2 cw3 = g_cw[e + 3];
        uint2 r0 = *(const uint2*)(hb + (size_t)cw0.x * 128);
        uint2 r1 = *(const uint2*)(hb + (size_t)cw1.x * 128);
        uint2 r2 = *(const uint2*)(hb + (size_t)cw2.x * 128);
        uint2 r3 = *(const uint2*)(hb + (size_t)cw3.x * 128);
        float w0 = __int_as_float(cw0.y), w1 = __int_as_float(cw1.y);
        float w2 = __int_as_float(cw2.y), w3 = __int_as_float(cw3.y);
        {
            float2 f01 = __half22float2(*reinterpret_cast<__half2*>(&r0.x));
            float2 f23 = __half22float2(*reinterpret_cast<__half2*>(&r0.y));
            accA.x += w0 * f01.x; accA.y += w0 * f01.y;
            accA.z += w0 * f23.x; accA.w += w0 * f23.y;
        }
        {
            float2 f01 = __half22float2(*reinterpret_cast<__half2*>(&r1.x));
            float2 f23 = __half22float2(*reinterpret_cast<__half2*>(&r1.y));
            accB.x += w1 * f01.x; accB.y += w1 * f01.y;
            accB.z += w1 * f23.x; accB.w += w1 * f23.y;
        }
        {
            float2 f01 = __half22float2(*reinterpret_cast<__half2*>(&r2.x));
            float2 f23 = __half22float2(*reinterpret_cast<__half2*>(&r2.y));
            accA.x += w2 * f01.x; accA.y += w2 * f01.y;
            accA.z += w2 * f23.x; accA.w += w2 * f23.y;
        }
        {
            float2 f01 = __half22float2(*reinterpret_cast<__half2*>(&r3.x));
            float2 f23 = __half22float2(*reinterpret_cast<__half2*>(&r3.y));
            accB.x += w3 * f01.x; accB.y += w3 * f01.y;
            accB.z += w3 * f23.x; accB.w += w3 * f23.y;
        }
    }
    for (; e < end; e++) {
        int2 cw = g_cw[e];
        float wt = __int_as_float(cw.y);
        uint2 raw = *(const uint2*)(hb + (size_t)cw.x * 128);
        float2 f01 = __half22float2(*reinterpret_cast<__half2*>(&raw.x));
        float2 f23 = __half22float2(*reinterpret_cast<__half2*>(&raw.y));
        accA.x += wt * f01.x; accA.y += wt * f01.y;
        accA.z += wt * f23.x; accA.w += wt * f23.y;
    }
    accA.x += accB.x; accA.y += accB.y; accA.z += accB.z; accA.w += accB.w;

    float4 b = *(const float4*)(bias + lane * 4);
    __half2 p0 = __floats2half2_rn(fmaxf(accA.x + b.x, 0.f),
                                   fmaxf(accA.y + b.y, 0.f));
    __half2 p1 = __floats2half2_rn(fmaxf(accA.z + b.z, 0.f),
                                   fmaxf(accA.w + b.w, 0.f));
    *(uint2*)(g_a1 + (size_t)w * 128 + lane * 4) =
        make_uint2(*(uint32_t*)&p0, *(uint32_t*)&p1);
}

// ---------------------------------------------------------------------------
// SpMM layer 2: out = Ahat @ h2(fp16) + b2, F=64. Unroll x4.
// ---------------------------------------------------------------------------

__launch_bounds__(256)
__global__ void k_spmm2(const float* __restrict__ bias, float* __restrict__ out,
                        int n) {
    int w = (blockIdx.x * 256 + threadIdx.x) >> 5;
    int lane = threadIdx.x & 31;
    if (w >= n) return;
    int beg = g_rowstart[w], end = g_rowstart[w + 1];

    float2 accA = make_float2(0.f, 0.f);
    float2 accB = make_float2(0.f, 0.f);
    const __half* hb = g_h2 + lane * 2;

    int e = beg;
    for (; e + 4 <= end; e += 4) {
        int2 cw0 = g_cw[e + 0];
        int2 cw1 = g_cw[e + 1];
        int2 cw2 = g_cw[e + 2];
        int2 cw3 = g_cw[e + 3];
        uint32_t r0 = *(const uint32_t*)(hb + (size_t)cw0.x * 64);
        uint32_t r1 = *(const uint32_t*)(hb + (size_t)cw1.x * 64);
        uint32_t r2 = *(const uint32_t*)(hb + (size_t)cw2.x * 64);
        uint32_t r3 = *(const uint32_t*)(hb + (size_t)cw3.x * 64);
        float w0 = __int_as_float(cw0.y), w1 = __int_as_float(cw1.y);
        float w2 = __int_as_float(cw2.y), w3 = __int_as_float(cw3.y);
        float2 v0 = __half22float2(*reinterpret_cast<__half2*>(&r0));
        float2 v1 = __half22float2(*reinterpret_cast<__half2*>(&r1));
        float2 v2 = __half22float2(*reinterpret_cast<__half2*>(&r2));
        float2 v3 = __half22float2(*reinterpret_cast<__half2*>(&r3));
        accA.x += w0 * v0.x; accA.y += w0 * v0.y;
        accB.x += w1 * v1.x; accB.y += w1 * v1.y;
        accA.x += w2 * v2.x; accA.y += w2 * v2.y;
        accB.x += w3 * v3.x; accB.y += w3 * v3.y;
    }
    for (; e < end; e++) {
        int2 cw = g_cw[e];
        float wt = __int_as_float(cw.y);
        uint32_t raw = *(const uint32_t*)(hb + (size_t)cw.x * 64);
        float2 v = __half22float2(*reinterpret_cast<__half2*>(&raw));
        accA.x += wt * v.x; accA.y += wt * v.y;
    }
    accA.x += accB.x; accA.y += accB.y;

    float2 b = *(const float2*)(bias + lane * 2);
    accA.x += b.x; accA.y += b.y;
    *(float2*)(out + (size_t)w * 64 + lane * 2) = accA;
}

// ---------------------------------------------------------------------------

extern "C" void kernel_launch(void* const* d_in, const int* in_sizes, int n_in,
                              void* d_out, int out_size) {
    const float* x = (const float*)d_in[0];
    const int* ei = (const int*)d_in[1];      // int32
    const float* W1 = (const float*)d_in[2];
    const float* b1 = (const float*)d_in[3];
    const float* W2 = (const float*)d_in[4];
    const float* b2 = (const float*)d_in[5];
    float* out = (float*)d_out;

    const int N = in_sizes[0] / 256;   // 100000
    const int E = in_sizes[1] / 2;     // 1600000
    const int* src = ei;
    const int* dst = ei + E;
    const int NB = (N + 1023) / 1024;

    // Fork a side stream for the CSR build so it overlaps with GEMM1.
    cudaStream_t s2;
    cudaStreamCreateWithFlags(&s2, cudaStreamNonBlocking);
    cudaEvent_t evFork, evJoin;
    cudaEventCreateWithFlags(&evFork, cudaEventDisableTiming);
    cudaEventCreateWithFlags(&evJoin, cudaEventDisableTiming);

    // #1 (main): W convert + deg init — prerequisite for both branches
    k_wcvt_init<<<(N + 255) / 256, 256>>>(W1, W2, N);
    cudaEventRecord(evFork, 0);
    cudaStreamWaitEvent(s2, evFork, 0);

    // CSR branch (s2): count -> scan1 -> scanfill -> fill_edges
    k_count<<<(E + 255) / 256, 256, 0, s2>>>(dst, E);
    k_scan1<<<NB, 1024, 0, s2>>>(N);
    k_scanfill<<<NB, 1024, 0, s2>>>(N, NB);
    k_fill_edges<<<(E + 255) / 256, 256, 0, s2>>>(src, dst, E);
    cudaEventRecord(evJoin, s2);

    // GEMM branch (main): h1 = x @ W1, concurrent with CSR build
    k_hgemm1<<<(N + 127) / 128, 256>>>(x, N);

    // join: spmm1 needs both h1 and the CSR
    cudaStreamWaitEvent(0, evJoin, 0);

    // a1 = relu(Ahat h1 + b1), fp16
    k_spmm1<<<((N * 32) + 255) / 256, 256>>>(b1, N);

    // h2 = a1 @ W2
    k_hgemm2<<<(N + 127) / 128, 256>>>(N);

    // out = Ahat h2 + b2
    k_spmm2<<<((N * 32) + 255) / 256, 256>>>(b2, out, N);
}

// round 16
// speedup vs baseline: 1.0223x; 1.0223x over previous
#include <cuda_runtime.h>
#include <cuda_fp16.h>
#include <cstdint>
#include <cstddef>

// ---------------------------------------------------------------------------
// GCN 2-layer forward on GB300 — fp16 HMMA GEMMs + gather SpMM.
//   h1 = x @ W1           (fp16 HMMA, BM=128)              [k_hgemm1]
//   a1 = relu(Ahat h1+b1) (fp16-stored)                    [k_spmm1]
//   h2 = a1 @ W2          (fp16 HMMA, fp16 A path)         [k_hgemm2]
//   out = Ahat h2 + b2    (fp32 out)                       [k_spmm2]
// R16: SpMM loops back to R14 form (R15 unroll regressed). spmm1/hgemm2
// split into two node-halves and pipelined across streams: hgemm2(half0)
// runs concurrently with spmm1(half1). CSR build still overlaps GEMM1.
// ---------------------------------------------------------------------------

#define NNODES 100000
#define NEDGES 1600000
#define NNZ    (NNODES + NEDGES)

__device__ int   g_deg[NNODES];
__device__ int   g_fill[NNODES];
__device__ int   g_rowstart[NNODES + 1];
__device__ int   g_bsums[256];
__device__ float g_dinv[NNODES];
__device__ int2  g_cw[NNZ];                     // .x = col, .y = wgt bits
__device__ __half g_h1[(size_t)NNODES * 128];   // h1 (fp16)
__device__ __half g_a1[(size_t)NNODES * 128];   // a1 (fp16)
__device__ __half g_h2[(size_t)NNODES * 64];    // h2 (fp16)
// W transposed K-major [N][K], fp16
__device__ __half g_w1[128 * 256];
__device__ __half g_w2[64 * 128];

// ------------------------------ helpers ------------------------------------

__device__ __forceinline__ uint32_t smem_u32(const void* p) {
    uint32_t a;
    asm("{ .reg .u64 t; cvta.to.shared.u64 t, %1; cvt.u32.u64 %0, t; }"
        : "=r"(a) : "l"(p));
    return a;
}

#define LDMATRIX_X4(r, addr) \
    asm volatile("ldmatrix.sync.aligned.m8n8.x4.shared.b16 {%0,%1,%2,%3}, [%4];" \
                 : "=r"((r)[0]), "=r"((r)[1]), "=r"((r)[2]), "=r"((r)[3]) \
                 : "r"(addr))

#define MMA_F16(c, a, b0, b1) \
    asm volatile( \
        "mma.sync.aligned.m16n8k16.row.col.f32.f16.f16.f32 " \
        "{%0,%1,%2,%3}, {%4,%5,%6,%7}, {%8,%9}, {%0,%1,%2,%3};" \
        : "+f"((c)[0]), "+f"((c)[1]), "+f"((c)[2]), "+f"((c)[3]) \
        : "r"((a)[0]), "r"((a)[1]), "r"((a)[2]), "r"((a)[3]), \
          "r"(b0), "r"(b1))

// ldmatrix x4 address, 64B-row buffer: swizzle kg ^= (row>>1)&3
__device__ __forceinline__ uint32_t lm_addr64(uint32_t buf, int rowbase, int ks,
                                              int lane) {
    int row = rowbase + (lane & 15);
    int kg = ks * 2 + (lane >> 4);
    return buf + row * 64 + (((kg ^ ((row >> 1) & 3))) << 4);
}

// ---------------------------------------------------------------------------
// CSR construction
// ---------------------------------------------------------------------------

// W convert (both layers) + deg init, one launch
__global__ void k_wcvt_init(const float* __restrict__ W1,
                            const float* __restrict__ W2, int n) {
    int idx = blockIdx.x * blockDim.x + threadIdx.x;
    if (idx < 128 * 256) {                 // W1: K=256, N=128
        int nn = idx / 256, k = idx % 256;
        g_w1[idx] = __float2half_rn(W1[k * 128 + nn]);
    } else if (idx < 128 * 256 + 64 * 128) {  // W2: K=128, N=64
        int j = idx - 128 * 256;
        int nn = j / 128, k = j % 128;
        g_w2[j] = __float2half_rn(W2[k * 64 + nn]);
    }
    if (idx < n) g_deg[idx] = 1;           // self loop
}

__global__ void k_count(const int* __restrict__ dst, int e) {
    int i = blockIdx.x * blockDim.x + threadIdx.x;
    if (i < e) atomicAdd(&g_deg[dst[i]], 1);
}

__global__ void k_scan1(int n) {
    __shared__ int s[1024];
    int gid = blockIdx.x * 1024 + threadIdx.x;
    int v = (gid < n) ? g_deg[gid] : 0;
    s[threadIdx.x] = v;
    __syncthreads();
    for (int off = 1; off < 1024; off <<= 1) {
        int t = (threadIdx.x >= off) ? s[threadIdx.x - off] : 0;
        __syncthreads();
        s[threadIdx.x] += t;
        __syncthreads();
    }
    if (gid < n) g_rowstart[gid] = s[threadIdx.x] - v;
    if (threadIdx.x == 1023) g_bsums[blockIdx.x] = s[1023];
}

__global__ void k_scanfill(int n, int nb) {
    __shared__ int soff;
    int gid = blockIdx.x * 1024 + threadIdx.x;
    if (threadIdx.x == 0) {
        int o = 0;
        for (int b = 0; b < (int)blockIdx.x; b++) o += g_bsums[b];
        soff = o;
    }
    __syncthreads();
    if (gid < n) {
        int rs = g_rowstart[gid] + soff;
        g_rowstart[gid] = rs;
        float d = rsqrtf((float)g_deg[gid]);
        g_dinv[gid] = d;
        g_cw[rs] = make_int2(gid, __float_as_int(d * d));
        g_fill[gid] = 1;
    }
    if (gid == 0) {
        int o = 0;
        for (int b = 0; b < nb; b++) o += g_bsums[b];
        g_rowstart[n] = o;
    }
}

__global__ void k_fill_edges(const int* __restrict__ src,
                             const int* __restrict__ dst, int e) {
    int i = blockIdx.x * blockDim.x + threadIdx.x;
    if (i < e) {
        int s = src[i];
        int d = dst[i];
        int p = g_rowstart[d] + atomicAdd(&g_fill[d], 1);
        g_cw[p] = make_int2(s, __float_as_int(g_dinv[s] * g_dinv[d]));
    }
}

// ---------------------------------------------------------------------------
// GEMM1: h1[M,128] = x[M,256](fp32) @ W1, fp16 HMMA, BM=128, reg dbuf.
// ---------------------------------------------------------------------------

__global__ void __launch_bounds__(256, 2) k_hgemm1(const float* __restrict__ A,
                                                   int M) {
    constexpr int N_ = 128, K_ = 256;
    constexpr int NCHUNK = K_ / 32;
    constexpr int NT16 = N_ / 32;
    constexpr int NBQ = 2;
    constexpr int OFF_B = 8192;

    __shared__ __align__(128) char smem[8192 + N_ * 64];

    const __half* __restrict__ Bw = g_w1;
    const uint32_t sb = smem_u32(smem);
    const int tid = threadIdx.x;
    const int wid = tid >> 5, lane = tid & 31;
    const int wm = wid & 3, wn = wid >> 2;
    const int m0 = blockIdx.x * 128;

    float acc[2][N_ / 16][4];
#pragma unroll
    for (int i = 0; i < 2; i++)
#pragma unroll
        for (int j = 0; j < N_ / 16; j++)
#pragma unroll
            for (int q = 0; q < 4; q++) acc[i][j][q] = 0.f;

    const int a_row[4] = {tid >> 3, (tid + 256) >> 3, (tid + 512) >> 3,
                          (tid + 768) >> 3};
    const int a_f4 = tid & 7;

    float4 pa[4];
    uint4 pb[NBQ];
#pragma unroll
    for (int i = 0; i < 4; i++) {
        int gr = m0 + a_row[i];
        pa[i] = make_float4(0.f, 0.f, 0.f, 0.f);
        if (gr < M) pa[i] = *(const float4*)(A + (size_t)gr * K_ + a_f4 * 4);
    }
#pragma unroll
    for (int i = 0; i < NBQ; i++) {
        int idx = tid + i * 256;
        int row = idx >> 2, kg = idx & 3;
        pb[i] = *(const uint4*)(Bw + (size_t)row * K_ + kg * 8);
    }

    for (int chunk = 0; chunk < NCHUNK; chunk++) {
#pragma unroll
        for (int i = 0; i < 4; i++) {
            float4 v = pa[i];
            int row = a_row[i];
            __half2 p0 = __floats2half2_rn(v.x, v.y);
            __half2 p1 = __floats2half2_rn(v.z, v.w);
            int kg = a_f4 >> 1, half = a_f4 & 1;
            uint32_t byte = row * 64 + ((kg ^ ((row >> 1) & 3)) << 4) + half * 8;
            *(uint2*)(smem + byte) = make_uint2(*(uint32_t*)&p0, *(uint32_t*)&p1);
        }
#pragma unroll
        for (int i = 0; i < NBQ; i++) {
            int idx = tid + i * 256;
            int row = idx >> 2, kg = idx & 3;
            uint32_t byte = row * 64 + ((kg ^ ((row >> 1) & 3)) << 4);
            *(uint4*)(smem + OFF_B + byte) = pb[i];
        }
        __syncthreads();

        if (chunk + 1 < NCHUNK) {
            const int k0 = (chunk + 1) * 32;
#pragma unroll
            for (int i = 0; i < 4; i++) {
                int gr = m0 + a_row[i];
                pa[i] = make_float4(0.f, 0.f, 0.f, 0.f);
                if (gr < M)
                    pa[i] = *(const float4*)(A + (size_t)gr * K_ + k0 + a_f4 * 4);
            }
#pragma unroll
            for (int i = 0; i < NBQ; i++) {
                int idx = tid + i * 256;
                int row = idx >> 2, kg = idx & 3;
                pb[i] = *(const uint4*)(Bw + (size_t)row * K_ + k0 + kg * 8);
            }
        }

#pragma unroll
        for (int ks = 0; ks < 2; ks++) {
            uint32_t am[2][4];
#pragma unroll
            for (int mt = 0; mt < 2; mt++) {
                LDMATRIX_X4(am[mt], lm_addr64(sb, wm * 32 + mt * 16, ks, lane));
            }
#pragma unroll
            for (int nt = 0; nt < NT16; nt++) {
                uint32_t bm[4];
                LDMATRIX_X4(bm, lm_addr64(sb + OFF_B, wn * (N_ / 2) + nt * 16,
                                          ks, lane));
#pragma unroll
                for (int mt = 0; mt < 2; mt++) {
                    MMA_F16(acc[mt][nt * 2 + 0], am[mt], bm[0], bm[2]);
                    MMA_F16(acc[mt][nt * 2 + 1], am[mt], bm[1], bm[3]);
                }
            }
        }
        __syncthreads();
    }

#pragma unroll
    for (int mt = 0; mt < 2; mt++) {
#pragma unroll
        for (int nt8 = 0; nt8 < N_ / 16; nt8++) {
            const float* c = acc[mt][nt8];
            int row0 = m0 + wm * 32 + mt * 16 + (lane >> 2);
            int col = wn * (N_ / 2) + nt8 * 8 + 2 * (lane & 3);
            __half2 p0 = __floats2half2_rn(c[0], c[1]);
            __half2 p1 = __floats2half2_rn(c[2], c[3]);
            if (row0 < M)
                *(uint32_t*)(g_h1 + (size_t)row0 * N_ + col) = *(uint32_t*)&p0;
            if (row0 + 8 < M)
                *(uint32_t*)(g_h1 + (size_t)(row0 + 8) * N_ + col) = *(uint32_t*)&p1;
        }
    }
}

// ---------------------------------------------------------------------------
// GEMM2: h2[m,64] = a1[m,128](fp16) @ W2, rows [base, base+cnt), fp16 A path.
// ---------------------------------------------------------------------------

__global__ void __launch_bounds__(256, 2) k_hgemm2(int base, int M) {
    constexpr int N_ = 64, K_ = 128;
    constexpr int NCHUNK = K_ / 32;      // 4
    constexpr int NT16 = N_ / 32;        // 2
    constexpr int OFF_B = 8192;

    __shared__ __align__(128) char smem[8192 + N_ * 64];

    const __half* __restrict__ A = g_a1;
    const __half* __restrict__ Bw = g_w2;
    const uint32_t sb = smem_u32(smem);
    const int tid = threadIdx.x;
    const int wid = tid >> 5, lane = tid & 31;
    const int wm = wid & 3, wn = wid >> 2;
    const int m0 = base + blockIdx.x * 128;

    float acc[2][N_ / 16][4];
#pragma unroll
    for (int i = 0; i < 2; i++)
#pragma unroll
        for (int j = 0; j < N_ / 16; j++)
#pragma unroll
            for (int q = 0; q < 4; q++) acc[i][j][q] = 0.f;

    const int a_row[2] = {tid >> 2, (tid + 256) >> 2};
    const int a_kg = tid & 3;

    uint4 pa[2];
    uint4 pb;
#pragma unroll
    for (int i = 0; i < 2; i++) {
        int gr = m0 + a_row[i];
        pa[i] = make_uint4(0u, 0u, 0u, 0u);
        if (gr < M) pa[i] = *(const uint4*)(A + (size_t)gr * K_ + a_kg * 8);
    }
    {
        int row = tid >> 2, kg = tid & 3;
        pb = *(const uint4*)(Bw + (size_t)row * K_ + kg * 8);
    }

    for (int chunk = 0; chunk < NCHUNK; chunk++) {
#pragma unroll
        for (int i = 0; i < 2; i++) {
            int row = a_row[i];
            uint32_t byte = row * 64 + ((a_kg ^ ((row >> 1) & 3)) << 4);
            *(uint4*)(smem + byte) = pa[i];
        }
        {
            int row = tid >> 2, kg = tid & 3;
            uint32_t byte = row * 64 + ((kg ^ ((row >> 1) & 3)) << 4);
            *(uint4*)(smem + OFF_B + byte) = pb;
        }
        __syncthreads();

        if (chunk + 1 < NCHUNK) {
            const int k0 = (chunk + 1) * 32;
#pragma unroll
            for (int i = 0; i < 2; i++) {
                int gr = m0 + a_row[i];
                pa[i] = make_uint4(0u, 0u, 0u, 0u);
                if (gr < M)
                    pa[i] = *(const uint4*)(A + (size_t)gr * K_ + k0 + a_kg * 8);
            }
            int row = tid >> 2, kg = tid & 3;
            pb = *(const uint4*)(Bw + (size_t)row * K_ + k0 + kg * 8);
        }

#pragma unroll
        for (int ks = 0; ks < 2; ks++) {
            uint32_t am[2][4];
#pragma unroll
            for (int mt = 0; mt < 2; mt++) {
                LDMATRIX_X4(am[mt], lm_addr64(sb, wm * 32 + mt * 16, ks, lane));
            }
#pragma unroll
            for (int nt = 0; nt < NT16; nt++) {
                uint32_t bm[4];
                LDMATRIX_X4(bm, lm_addr64(sb + OFF_B, wn * (N_ / 2) + nt * 16,
                                          ks, lane));
#pragma unroll
                for (int mt = 0; mt < 2; mt++) {
                    MMA_F16(acc[mt][nt * 2 + 0], am[mt], bm[0], bm[2]);
                    MMA_F16(acc[mt][nt * 2 + 1], am[mt], bm[1], bm[3]);
                }
            }
        }
        __syncthreads();
    }

#pragma unroll
    for (int mt = 0; mt < 2; mt++) {
#pragma unroll
        for (int nt8 = 0; nt8 < N_ / 16; nt8++) {
            const float* c = acc[mt][nt8];
            int row0 = m0 + wm * 32 + mt * 16 + (lane >> 2);
            int col = wn * (N_ / 2) + nt8 * 8 + 2 * (lane & 3);
            __half2 p0 = __floats2half2_rn(c[0], c[1]);
            __half2 p1 = __floats2half2_rn(c[2], c[3]);
            if (row0 < M)
                *(uint32_t*)(g_h2 + (size_t)row0 * N_ + col) = *(uint32_t*)&p0;
            if (row0 + 8 < M)
                *(uint32_t*)(g_h2 + (size_t)(row0 + 8) * N_ + col) = *(uint32_t*)&p1;
        }
    }
}

// ---------------------------------------------------------------------------
// SpMM layer 1: a1 = relu(Ahat @ h1(fp16) + b1) for nodes [base, nend).
// warp/node, lane = 4 features. R14 loop form.
// ---------------------------------------------------------------------------

__launch_bounds__(256)
__global__ void k_spmm1(const float* __restrict__ bias, int base, int nend) {
    int w = base + ((blockIdx.x * 256 + threadIdx.x) >> 5);
    int lane = threadIdx.x & 31;
    if (w >= nend) return;
    int beg = g_rowstart[w], end = g_rowstart[w + 1];

    float4 acc = make_float4(0.f, 0.f, 0.f, 0.f);
    const __half* hb = g_h1 + lane * 4;
    for (int e = beg; e < end; e++) {
        int2 cw = g_cw[e];
        float wt = __int_as_float(cw.y);
        uint2 raw = *(const uint2*)(hb + (size_t)cw.x * 128);
        float2 f01 = __half22float2(*reinterpret_cast<__half2*>(&raw.x));
        float2 f23 = __half22float2(*reinterpret_cast<__half2*>(&raw.y));
        acc.x += wt * f01.x; acc.y += wt * f01.y;
        acc.z += wt * f23.x; acc.w += wt * f23.y;
    }
    float4 b = *(const float4*)(bias + lane * 4);
    __half2 p0 = __floats2half2_rn(fmaxf(acc.x + b.x, 0.f),
                                   fmaxf(acc.y + b.y, 0.f));
    __half2 p1 = __floats2half2_rn(fmaxf(acc.z + b.z, 0.f),
                                   fmaxf(acc.w + b.w, 0.f));
    *(uint2*)(g_a1 + (size_t)w * 128 + lane * 4) =
        make_uint2(*(uint32_t*)&p0, *(uint32_t*)&p1);
}

// ---------------------------------------------------------------------------
// SpMM layer 2: out = Ahat @ h2(fp16) + b2, F=64. R14 loop form.
// ---------------------------------------------------------------------------

__launch_bounds__(256)
__global__ void k_spmm2(const float* __restrict__ bias, float* __restrict__ out,
                        int n) {
    int w = (blockIdx.x * 256 + threadIdx.x) >> 5;
    int lane = threadIdx.x & 31;
    if (w >= n) return;
    int beg = g_rowstart[w], end = g_rowstart[w + 1];

    float2 acc = make_float2(0.f, 0.f);
    const __half* hb = g_h2 + lane * 2;
    for (int e = beg; e < end; e++) {
        int2 cw = g_cw[e];
        float wt = __int_as_float(cw.y);
        uint32_t raw = *(const uint32_t*)(hb + (size_t)cw.x * 64);
        float2 v = __half22float2(*reinterpret_cast<__half2*>(&raw));
        acc.x += wt * v.x; acc.y += wt * v.y;
    }
    float2 b = *(const float2*)(bias + lane * 2);
    acc.x += b.x; acc.y += b.y;
    *(float2*)(out + (size_t)w * 64 + lane * 2) = acc;
}

// ---------------------------------------------------------------------------

extern "C" void kernel_launch(void* const* d_in, const int* in_sizes, int n_in,
                              void* d_out, int out_size) {
    const float* x = (const float*)d_in[0];
    const int* ei = (const int*)d_in[1];      // int32
    const float* W1 = (const float*)d_in[2];
    const float* b1 = (const float*)d_in[3];
    const float* W2 = (const float*)d_in[4];
    const float* b2 = (const float*)d_in[5];
    float* out = (float*)d_out;

    const int N = in_sizes[0] / 256;   // 100000
    const int E = in_sizes[1] / 2;     // 1600000
    const int* src = ei;
    const int* dst = ei + E;
    const int NB = (N + 1023) / 1024;

    // node halves (128-aligned split for hgemm2 tiling)
    const int H0 = ((N / 2 + 127) / 128) * 128;   // 50048
    const int H1 = N - H0;

    cudaStream_t s2;
    cudaStreamCreateWithFlags(&s2, cudaStreamNonBlocking);
    cudaEvent_t evFork, evJoin, evA0, evG0;
    cudaEventCreateWithFlags(&evFork, cudaEventDisableTiming);
    cudaEventCreateWithFlags(&evJoin, cudaEventDisableTiming);
    cudaEventCreateWithFlags(&evA0, cudaEventDisableTiming);
    cudaEventCreateWithFlags(&evG0, cudaEventDisableTiming);

    // #1 (main): W convert + deg init — prerequisite for both branches
    k_wcvt_init<<<(N + 255) / 256, 256>>>(W1, W2, N);
    cudaEventRecord(evFork, 0);
    cudaStreamWaitEvent(s2, evFork, 0);

    // CSR branch (s2): count -> scan1 -> scanfill -> fill_edges
    k_count<<<(E + 255) / 256, 256, 0, s2>>>(dst, E);
    k_scan1<<<NB, 1024, 0, s2>>>(N);
    k_scanfill<<<NB, 1024, 0, s2>>>(N, NB);
    k_fill_edges<<<(E + 255) / 256, 256, 0, s2>>>(src, dst, E);
    cudaEventRecord(evJoin, s2);

    // GEMM branch (main): h1 = x @ W1, concurrent with CSR build
    k_hgemm1<<<(N + 127) / 128, 256>>>(x, N);

    // join: spmm1 needs both h1 and the CSR
    cudaStreamWaitEvent(0, evJoin, 0);

    // pipelined spmm1 / hgemm2 over two node-halves:
    //   main: spmm1(h0) -> spmm1(h1) -> hgemm2(h1)
    //   s2:              hgemm2(h0)   (concurrent with spmm1(h1))
    k_spmm1<<<((H0 * 32) + 255) / 256, 256>>>(b1, 0, H0);
    cudaEventRecord(evA0, 0);
    cudaStreamWaitEvent(s2, evA0, 0);
    k_hgemm2<<<H0 / 128, 256, 0, s2>>>(0, N);
    cudaEventRecord(evG0, s2);

    k_spmm1<<<((H1 * 32) + 255) / 256, 256>>>(b1, H0, N);
    k_hgemm2<<<(H1 + 127) / 128, 256>>>(H0, N);

    // spmm2 needs both hgemm2 halves
    cudaStreamWaitEvent(0, evG0, 0);
    k_spmm2<<<((N * 32) + 255) / 256, 256>>>(b2, out, N);
}